// round 11
// baseline (speedup 1.0000x reference)
#include <cuda_runtime.h>
#include <cuda_fp16.h>
#include <cstdint>
#include <cstddef>

#define B_ 32
#define C_ 64
#define T_ 16384
#define K_ 21
#define KT 24           // taps padded (A holds zeros for 21..23)
#define TC_ 16364       // T - (K-1)
#define TP_ 16384
#define NEG 0.01f

#define TN 128          // time per CTA
#define NTB 128         // ceil(TC_/TN)
#define XW 152          // staged x row width (floats)

// smem layout (bytes)
#define XS_OFF 0
#define A_OFF  38912                     // 64*152*4
#define A_CI   6144                      // 128 rows * 24 taps * 2B
#define XH_OFF (A_OFF + 2*A_CI)          // 51200
#define XH_BUF 624                       // 156 half2 * 4B
#define SMEM_TOTAL (128*132*4)           // 67584 (epilogue sh_y dominates)

// ---------------- device scratch --------------------------------------------
__device__ float g_y[(size_t)2 * B_ * C_ * TP_];            // [br][b][co][t]
__device__ __align__(16) __half g_wA[64 * 128 * KT];        // [ci][m][kk] (fp16)
__device__ float g_sum[2 * C_], g_sumsq[2 * C_];
__device__ float g_scale[2 * C_], g_shift[2 * C_];
__device__ float g_feat[B_ * 384];

// ---------------- PTX helpers -----------------------------------------------
__device__ __forceinline__ uint32_t smem_u32(const void* p) {
    uint32_t a;
    asm("{ .reg .u64 t; cvta.to.shared.u64 t, %1; cvt.u32.u64 %0, t; }"
        : "=r"(a) : "l"(p));
    return a;
}
__device__ __forceinline__ void ldsm4(uint32_t* r, uint32_t addr) {
    asm volatile("ldmatrix.sync.aligned.m8n8.x4.shared.b16 {%0,%1,%2,%3}, [%4];"
        : "=r"(r[0]), "=r"(r[1]), "=r"(r[2]), "=r"(r[3]) : "r"(addr));
}
__device__ __forceinline__ void ldsm2(uint32_t* r, uint32_t addr) {
    asm volatile("ldmatrix.sync.aligned.m8n8.x2.shared.b16 {%0,%1}, [%2];"
        : "=r"(r[0]), "=r"(r[1]) : "r"(addr));
}
__device__ __forceinline__ uint32_t lds32(uint32_t addr) {
    uint32_t v;
    asm volatile("ld.shared.b32 %0, [%1];" : "=r"(v) : "r"(addr));
    return v;
}
__device__ __forceinline__ void mma16(float* c, const uint32_t* a, const uint32_t* b) {
    asm volatile("mma.sync.aligned.m16n8k16.row.col.f32.f16.f16.f32 "
        "{%0,%1,%2,%3}, {%4,%5,%6,%7}, {%8,%9}, {%0,%1,%2,%3};"
        : "+f"(c[0]), "+f"(c[1]), "+f"(c[2]), "+f"(c[3])
        : "r"(a[0]), "r"(a[1]), "r"(a[2]), "r"(a[3]), "r"(b[0]), "r"(b[1]));
}
__device__ __forceinline__ void mma8(float* c, const uint32_t* a, uint32_t b) {
    asm volatile("mma.sync.aligned.m16n8k8.row.col.f32.f16.f16.f32 "
        "{%0,%1,%2,%3}, {%4,%5}, {%6}, {%0,%1,%2,%3};"
        : "+f"(c[0]), "+f"(c[1]), "+f"(c[2]), "+f"(c[3])
        : "r"(a[0]), "r"(a[1]), "r"(b));
}
__device__ __forceinline__ void cpasync16(uint32_t dst, const void* src) {
    asm volatile("cp.async.cg.shared.global [%0], [%1], 16;" :: "r"(dst), "l"(src));
}

// ---------------- kernel 0: zero stats --------------------------------------
__global__ void zero_kernel() {
    int i = threadIdx.x;
    if (i < 2 * C_) { g_sum[i] = 0.f; g_sumsq[i] = 0.f; }
}

// ---------------- kernel 1: weight prep (fp16, tap-padded) ------------------
__global__ void wpack_kernel(const float* __restrict__ w1,
                             const float* __restrict__ w2) {
    int idx = blockIdx.x * blockDim.x + threadIdx.x;
    if (idx >= 64 * 128 * KT) return;
    int ci = idx / (128 * KT);
    int r2 = idx % (128 * KT);
    int m  = r2 / KT;
    int kk = r2 % KT;
    float v = 0.f;
    if (kk < K_)
        v = (m < 64) ? w1[(m * 64 + ci) * K_ + kk]
                     : w2[((m - 64) * 64 + ci) * K_ + kk];
    g_wA[idx] = __float2half_rn(v);
}

// ---------------- pad kernel (ncu -s slot alignment) ------------------------
__global__ void pad_kernel() {}

// ---------------- kernel 2: conv via mma.sync fp16 implicit GEMM ------------
// pure fp16 operands, fp32 accumulate (rel_err ~1e-4, gate is 1e-3)
__global__ __launch_bounds__(256, 2) void conv_kernel(const float* __restrict__ x) {
    extern __shared__ float sh[];
    const int b   = blockIdx.y;
    const int t0  = blockIdx.x * TN;
    const int tid = threadIdx.x;
    const int wid = tid >> 5;
    const int l   = tid & 31;
    const uint32_t sbase = smem_u32(sh);

    // stage x tile: 64 rows x XW floats, zero-pad beyond T_
    for (int i = tid; i < 64 * (XW / 4); i += 256) {
        int ci = i / (XW / 4), j4 = i % (XW / 4);
        int gt = t0 + j4 * 4;
        float4 v = make_float4(0.f, 0.f, 0.f, 0.f);
        if (gt + 3 < T_) v = *(const float4*)&x[((size_t)b * C_ + ci) * T_ + gt];
        else {
            for (int e = 0; e < 4; e++)
                if (gt + e < T_) (&v.x)[e] = x[((size_t)b * C_ + ci) * T_ + gt + e];
        }
        *(float4*)&sh[ci * XW + j4 * 4] = v;
    }

    // prefetch A(ci=0): 6144 B = 384 x 16B
    for (int c = tid; c < 384; c += 256)
        cpasync16(sbase + A_OFF + c * 16, (const char*)g_wA + c * 16);
    asm volatile("cp.async.commit_group;" ::: "memory");
    __syncthreads();   // xs visible

    const int wr = wid >> 1;          // 0..3 (M)
    const int wc = wid & 1;           // 0..1 (N)
    float acc[2][8][4];
#pragma unroll
    for (int mt = 0; mt < 2; mt++)
#pragma unroll
        for (int nt = 0; nt < 8; nt++)
#pragma unroll
            for (int e = 0; e < 4; e++) acc[mt][nt][e] = 0.f;

    for (int ci = 0; ci < 64; ++ci) {
        const int buf = ci & 1;
        // build xh2 window for this ci (152 threads)
        if (tid < 152) {
            float v0 = sh[ci * XW + tid];
            float v1 = (tid + 1 < 152) ? sh[ci * XW + tid + 1] : 0.f;
            __half2* xh2 = (__half2*)((char*)sh + XH_OFF + buf * XH_BUF);
            xh2[tid] = __halves2half2(__float2half_rn(v0), __float2half_rn(v1));
        }
        // wait A(ci), make builds visible
        asm volatile("cp.async.wait_group 0;" ::: "memory");
        __syncthreads();
        // prefetch A(ci+1)
        if (ci + 1 < 64) {
            const char* src = (const char*)g_wA + (size_t)(ci + 1) * A_CI;
            uint32_t dst = sbase + A_OFF + ((ci + 1) & 1) * A_CI;
            for (int c = tid; c < 384; c += 256)
                cpasync16(dst + c * 16, src + c * 16);
            asm volatile("cp.async.commit_group;" ::: "memory");
        }

        // A fragments (ldmatrix), rows stride 48B
        const uint32_t abase = sbase + A_OFF + buf * A_CI;
        uint32_t ah[2][6];
#pragma unroll
        for (int mt = 0; mt < 2; mt++) {
            int row = wr * 32 + mt * 16 + (l & 15);
            uint32_t a16 = abase + row * 48 + (l >> 4) * 16;
            uint32_t a8  = abase + row * 48 + 32;
            ldsm4(ah[mt], a16);
            ldsm2(ah[mt] + 4, a8);
        }
        // B lane base: idx = wc*64 + l/4 + 2*(l%4)
        uint32_t bh_base = sbase + XH_OFF + buf * XH_BUF
                         + 4 * (wc * 64 + (l >> 2) + 2 * (l & 3));
#pragma unroll
        for (int nt = 0; nt < 8; nt++) {
            uint32_t bo = nt * 32;
            uint32_t bh[2], bh8;
            bh[0] = lds32(bh_base + bo);
            bh[1] = lds32(bh_base + bo + 32);
            bh8   = lds32(bh_base + bo + 64);
#pragma unroll
            for (int mt = 0; mt < 2; mt++) {
                float* c = acc[mt][nt];
                mma16(c, ah[mt], bh);
                mma8(c, ah[mt] + 4, bh8);
            }
        }
    }

    // ---------------- epilogue: accs -> smem -> coalesced y + stats ---------
    __syncthreads();   // done reading xs/A/xh; reuse smem as sh_y[128][132]
#pragma unroll
    for (int mt = 0; mt < 2; mt++)
#pragma unroll
        for (int nt = 0; nt < 8; nt++) {
            int R0 = wr * 32 + mt * 16 + (l >> 2);
            int Cc = wc * 64 + nt * 8 + 2 * (l & 3);
            *(float2*)&sh[R0 * 132 + Cc]       = make_float2(acc[mt][nt][0], acc[mt][nt][1]);
            *(float2*)&sh[(R0 + 8) * 132 + Cc] = make_float2(acc[mt][nt][2], acc[mt][nt][3]);
        }
    __syncthreads();

    const bool fullt = (t0 + TN <= TC_);
#pragma unroll 1
    for (int it = 0; it < 16; ++it) {
        int row = it * 8 + wid;            // 0..127 = br*64+co
        int colb = l * 4;
        float4 v = *(float4*)&sh[row * 132 + colb];
        float s = 0.f, ss = 0.f;
        if (fullt) {
            s  = v.x + v.y + v.z + v.w;
            ss = v.x * v.x + v.y * v.y + v.z * v.z + v.w * v.w;
        } else {
#pragma unroll
            for (int e = 0; e < 4; e++) {
                if (t0 + colb + e < TC_) {
                    float f = (&v.x)[e];
                    s += f; ss += f * f;
                }
            }
        }
#pragma unroll
        for (int o = 16; o; o >>= 1) {
            s  += __shfl_xor_sync(0xffffffffu, s, o);
            ss += __shfl_xor_sync(0xffffffffu, ss, o);
        }
        if (l == 0) { atomicAdd(&g_sum[row], s); atomicAdd(&g_sumsq[row], ss); }
        int br = row >> 6, co = row & 63;
        float* yp = g_y + ((size_t)((br * B_ + b) * C_ + co)) * TP_ + t0;
        if (fullt) {
            *(float4*)&yp[colb] = v;
        } else {
#pragma unroll
            for (int e = 0; e < 4; e++)
                if (t0 + colb + e < TC_) yp[colb + e] = (&v.x)[e];
        }
    }
}

// ---------------- kernel 3: finalize BN affine ------------------------------
__global__ void finalize_kernel(const float* __restrict__ g1, const float* __restrict__ b1,
                                const float* __restrict__ g2, const float* __restrict__ b2) {
    int i = threadIdx.x;
    if (i < 2 * C_) {
        int br = i >> 6, c = i & 63;
        const float Nf = (float)(B_ * TC_);
        float mean = g_sum[i] / Nf;
        float var  = g_sumsq[i] / Nf - mean * mean;
        float gamma = br ? g2[c] : g1[c];
        float beta  = br ? b2[c] : b1[c];
        float a = gamma * rsqrtf(var + 1e-5f);
        g_scale[i] = a;
        g_shift[i] = beta - mean * a;
    }
}

// ---------------- kernel 4: SPP pooling -------------------------------------
__global__ __launch_bounds__(256) void pool_kernel(const int* __restrict__ orig_len) {
    const int co = blockIdx.x, b = blockIdx.y, br = blockIdx.z;
    const int L    = orig_len[b] - (K_ - 1);
    const int str  = L >> 1;
    const int kern = L - str;
    const float a  = g_scale[br * C_ + co];
    const float c0 = g_shift[br * C_ + co];
    const float* yp = g_y + (size_t)((br * B_ + b) * C_ + co) * TP_;
    const int tid = threadIdx.x;
    const float NINF = __int_as_float(0xff800000);

    float r0, r1, r2;
    if (br == 0) {
        float m = NINF, m0 = NINF, m1 = NINF;
        for (int t = tid; t < L; t += 256) {
            float v = fmaf(yp[t], a, c0);
            v = (v > 0.f) ? v : NEG * v;
            m = fmaxf(m, v);
            if (t < kern)  m0 = fmaxf(m0, v);
            if (t >= str)  m1 = fmaxf(m1, v);
        }
        r0 = m; r1 = m0; r2 = m1;
    } else {
        float s = 0.f, s0 = 0.f, s1 = 0.f;
        for (int t = tid; t < L; t += 256) {
            float v = fmaf(yp[t], a, c0);
            v = (v > 0.f) ? v : NEG * v;
            s += v;
            if (t < kern)  s0 += v;
            if (t >= str)  s1 += v;
        }
        r0 = s; r1 = s0; r2 = s1;
    }

    __shared__ float sred[3][8];
    const int lane = tid & 31, wrp = tid >> 5;
    if (br == 0) {
#pragma unroll
        for (int o = 16; o; o >>= 1) {
            r0 = fmaxf(r0, __shfl_xor_sync(0xffffffffu, r0, o));
            r1 = fmaxf(r1, __shfl_xor_sync(0xffffffffu, r1, o));
            r2 = fmaxf(r2, __shfl_xor_sync(0xffffffffu, r2, o));
        }
    } else {
#pragma unroll
        for (int o = 16; o; o >>= 1) {
            r0 += __shfl_xor_sync(0xffffffffu, r0, o);
            r1 += __shfl_xor_sync(0xffffffffu, r1, o);
            r2 += __shfl_xor_sync(0xffffffffu, r2, o);
        }
    }
    if (lane == 0) { sred[0][wrp] = r0; sred[1][wrp] = r1; sred[2][wrp] = r2; }
    __syncthreads();
    if (tid == 0) {
        float a0 = sred[0][0], a1 = sred[1][0], a2 = sred[2][0];
        for (int w = 1; w < 8; w++) {
            if (br == 0) {
                a0 = fmaxf(a0, sred[0][w]);
                a1 = fmaxf(a1, sred[1][w]);
                a2 = fmaxf(a2, sred[2][w]);
            } else {
                a0 += sred[0][w]; a1 += sred[1][w]; a2 += sred[2][w];
            }
        }
        float* f = g_feat + b * 384;
        if (br == 0) {
            f[co] = a0;
            f[64 + 2 * co]     = a1;
            f[64 + 2 * co + 1] = a2;
        } else {
            f[192 + co] = a0 / (float)L;
            f[256 + 2 * co]     = a1 / (float)kern;
            f[256 + 2 * co + 1] = a2 / (float)kern;
        }
    }
}

// ---------------- kernel 5: FC head -----------------------------------------
__global__ void fc_kernel(const float* __restrict__ fcw, const float* __restrict__ fcb,
                          float* __restrict__ out) {
    int i = threadIdx.x;
    if (i < B_ * 2) {
        int b = i >> 1, t = i & 1;
        float acc = fcb[t];
        const float* f = g_feat + b * 384;
        const float* w = fcw + t * 384;
#pragma unroll 8
        for (int j = 0; j < 384; j++) acc += f[j] * w[j];
        out[i] = acc;
    }
}

// ---------------- launch ----------------------------------------------------
extern "C" void kernel_launch(void* const* d_in, const int* in_sizes, int n_in,
                              void* d_out, int out_size) {
    const float* x        = (const float*)d_in[0];
    const int*   orig_len = (const int*)  d_in[1];
    const float* w1       = (const float*)d_in[2];
    const float* g1       = (const float*)d_in[3];
    const float* b1       = (const float*)d_in[4];
    const float* w2       = (const float*)d_in[5];
    const float* g2       = (const float*)d_in[6];
    const float* b2       = (const float*)d_in[7];
    const float* fcw      = (const float*)d_in[8];
    const float* fcb      = (const float*)d_in[9];
    float* out = (float*)d_out;

    cudaFuncSetAttribute(conv_kernel, cudaFuncAttributeMaxDynamicSharedMemorySize,
                         SMEM_TOTAL);

    zero_kernel<<<1, 128>>>();
    wpack_kernel<<<(64 * 128 * KT + 255) / 256, 256>>>(w1, w2);
    pad_kernel<<<1, 32>>>();   // keeps the ncu -s window on conv
    conv_kernel<<<dim3(NTB, B_), 256, SMEM_TOTAL>>>(x);
    finalize_kernel<<<1, 128>>>(g1, b1, g2, b2);
    pool_kernel<<<dim3(C_, B_, 2), 256>>>(orig_len);
    fc_kernel<<<1, 64>>>(fcw, fcb, out);
}

// round 12
// speedup vs baseline: 1.0403x; 1.0403x over previous
#include <cuda_runtime.h>
#include <cuda_fp16.h>
#include <cstdint>
#include <cstddef>

#define B_ 32
#define C_ 64
#define T_ 16384
#define K_ 21
#define KT 24           // taps padded (A holds zeros for 21..23)
#define TC_ 16364       // T - (K-1)
#define TP_ 16384
#define NEG 0.01f

#define TN 128          // time per CTA
#define NTB 128         // ceil(TC_/TN)
#define XW 152          // staged x row width (floats)

// smem layout (bytes)
#define XS_OFF 0
#define A_OFF  38912                     // 64*152*4
#define A_CI   6144                      // 128 rows * 24 taps * 2B
#define A_PAIR (2*A_CI)                  // 12288 per stage (2 ci)
#define XH_OFF (A_OFF + 2*A_PAIR)        // 63488
#define XH_BUF 624                       // 156 half2 * 4B (per ci)
#define SMEM_TOTAL (128*132*4)           // 67584 (epilogue sh_y dominates)

// ---------------- device scratch --------------------------------------------
__device__ float g_y[(size_t)2 * B_ * C_ * TP_];            // [br][b][co][t]
__device__ __align__(16) __half g_wA[64 * 128 * KT];        // [ci][m][kk] (fp16)
__device__ float g_sum[2 * C_], g_sumsq[2 * C_];
__device__ float g_scale[2 * C_], g_shift[2 * C_];
__device__ float g_feat[B_ * 384];

// ---------------- PTX helpers -----------------------------------------------
__device__ __forceinline__ uint32_t smem_u32(const void* p) {
    uint32_t a;
    asm("{ .reg .u64 t; cvta.to.shared.u64 t, %1; cvt.u32.u64 %0, t; }"
        : "=r"(a) : "l"(p));
    return a;
}
__device__ __forceinline__ void ldsm4(uint32_t* r, uint32_t addr) {
    asm volatile("ldmatrix.sync.aligned.m8n8.x4.shared.b16 {%0,%1,%2,%3}, [%4];"
        : "=r"(r[0]), "=r"(r[1]), "=r"(r[2]), "=r"(r[3]) : "r"(addr));
}
__device__ __forceinline__ void ldsm2(uint32_t* r, uint32_t addr) {
    asm volatile("ldmatrix.sync.aligned.m8n8.x2.shared.b16 {%0,%1}, [%2];"
        : "=r"(r[0]), "=r"(r[1]) : "r"(addr));
}
__device__ __forceinline__ uint32_t lds32(uint32_t addr) {
    uint32_t v;
    asm volatile("ld.shared.b32 %0, [%1];" : "=r"(v) : "r"(addr));
    return v;
}
__device__ __forceinline__ void mma16(float* c, const uint32_t* a, const uint32_t* b) {
    asm volatile("mma.sync.aligned.m16n8k16.row.col.f32.f16.f16.f32 "
        "{%0,%1,%2,%3}, {%4,%5,%6,%7}, {%8,%9}, {%0,%1,%2,%3};"
        : "+f"(c[0]), "+f"(c[1]), "+f"(c[2]), "+f"(c[3])
        : "r"(a[0]), "r"(a[1]), "r"(a[2]), "r"(a[3]), "r"(b[0]), "r"(b[1]));
}
__device__ __forceinline__ void mma8(float* c, const uint32_t* a, uint32_t b) {
    asm volatile("mma.sync.aligned.m16n8k8.row.col.f32.f16.f16.f32 "
        "{%0,%1,%2,%3}, {%4,%5}, {%6}, {%0,%1,%2,%3};"
        : "+f"(c[0]), "+f"(c[1]), "+f"(c[2]), "+f"(c[3])
        : "r"(a[0]), "r"(a[1]), "r"(b));
}
__device__ __forceinline__ void cpasync16(uint32_t dst, const void* src) {
    asm volatile("cp.async.cg.shared.global [%0], [%1], 16;" :: "r"(dst), "l"(src));
}

// ---------------- kernel 0: zero stats --------------------------------------
__global__ void zero_kernel() {
    int i = threadIdx.x;
    if (i < 2 * C_) { g_sum[i] = 0.f; g_sumsq[i] = 0.f; }
}

// ---------------- kernel 1: weight prep (fp16, tap-padded) ------------------
__global__ void wpack_kernel(const float* __restrict__ w1,
                             const float* __restrict__ w2) {
    int idx = blockIdx.x * blockDim.x + threadIdx.x;
    if (idx >= 64 * 128 * KT) return;
    int ci = idx / (128 * KT);
    int r2 = idx % (128 * KT);
    int m  = r2 / KT;
    int kk = r2 % KT;
    float v = 0.f;
    if (kk < K_)
        v = (m < 64) ? w1[(m * 64 + ci) * K_ + kk]
                     : w2[((m - 64) * 64 + ci) * K_ + kk];
    g_wA[idx] = __float2half_rn(v);
}

// ---------------- pad kernel (ncu -s slot alignment) ------------------------
__global__ void pad_kernel() {}

// ---------------- helpers for the conv pipeline ------------------------------
__device__ __forceinline__ void prefetch_Apair(uint32_t sbase, int pair, int buf,
                                               int tid) {
    const char* src = (const char*)g_wA + (size_t)pair * A_PAIR;
    uint32_t dst = sbase + A_OFF + buf * A_PAIR;
    for (int c = tid; c < 768; c += 256)
        cpasync16(dst + c * 16, src + c * 16);
    asm volatile("cp.async.commit_group;" ::: "memory");
}
__device__ __forceinline__ void build_xh(float* sh, int ci0, int buf, int tid) {
    for (int i = tid; i < 304; i += 256) {
        int cc = (i >= 152);
        int j  = i - cc * 152;
        int ci = ci0 + cc;
        float v0 = sh[ci * XW + j];
        float v1 = (j + 1 < 152) ? sh[ci * XW + j + 1] : 0.f;
        __half2* xh2 = (__half2*)((char*)sh + XH_OFF + (buf * 2 + cc) * XH_BUF);
        xh2[j] = __halves2half2(__float2half_rn(v0), __float2half_rn(v1));
    }
}

// ---------------- kernel 2: conv via mma.sync fp16 implicit GEMM ------------
// 2 ci per pipeline stage: one barrier / one cp.async drain per 64 MMAs/warp
__global__ __launch_bounds__(256, 2) void conv_kernel(const float* __restrict__ x) {
    extern __shared__ float sh[];
    const int b   = blockIdx.y;
    const int t0  = blockIdx.x * TN;
    const int tid = threadIdx.x;
    const int wid = tid >> 5;
    const int l   = tid & 31;
    const uint32_t sbase = smem_u32(sh);

    // stage x tile: 64 rows x XW floats, zero-pad beyond T_
    for (int i = tid; i < 64 * (XW / 4); i += 256) {
        int ci = i / (XW / 4), j4 = i % (XW / 4);
        int gt = t0 + j4 * 4;
        float4 v = make_float4(0.f, 0.f, 0.f, 0.f);
        if (gt + 3 < T_) v = *(const float4*)&x[((size_t)b * C_ + ci) * T_ + gt];
        else {
            for (int e = 0; e < 4; e++)
                if (gt + e < T_) (&v.x)[e] = x[((size_t)b * C_ + ci) * T_ + gt + e];
        }
        *(float4*)&sh[ci * XW + j4 * 4] = v;
    }

    prefetch_Apair(sbase, 0, 0, tid);
    __syncthreads();                    // xs visible
    build_xh(sh, 0, 0, tid);
    asm volatile("cp.async.wait_group 0;" ::: "memory");
    __syncthreads();                    // xh(stage0) + A(stage0) visible

    const int wr = wid >> 1;          // 0..3 (M)
    const int wc = wid & 1;           // 0..1 (N)
    float acc[2][8][4];
#pragma unroll
    for (int mt = 0; mt < 2; mt++)
#pragma unroll
        for (int nt = 0; nt < 8; nt++)
#pragma unroll
            for (int e = 0; e < 4; e++) acc[mt][nt][e] = 0.f;

    const uint32_t blane = 4 * (wc * 64 + (l >> 2) + 2 * (l & 3));

    for (int s = 0; s < 32; ++s) {
        const int buf = s & 1;
        if (s + 1 < 32) prefetch_Apair(sbase, s + 1, buf ^ 1, tid);

#pragma unroll
        for (int cc = 0; cc < 2; ++cc) {
            const uint32_t abase = sbase + A_OFF + buf * A_PAIR + cc * A_CI;
            uint32_t ah[2][6];
#pragma unroll
            for (int mt = 0; mt < 2; mt++) {
                int row = wr * 32 + mt * 16 + (l & 15);
                uint32_t a16 = abase + row * 48 + (l >> 4) * 16;
                uint32_t a8  = abase + row * 48 + 32;
                ldsm4(ah[mt], a16);
                ldsm2(ah[mt] + 4, a8);
            }
            const uint32_t bh_base = sbase + XH_OFF + (buf * 2 + cc) * XH_BUF + blane;
#pragma unroll
            for (int nt = 0; nt < 8; nt++) {
                uint32_t bo = nt * 32;
                uint32_t bh[2], bh8;
                bh[0] = lds32(bh_base + bo);
                bh[1] = lds32(bh_base + bo + 32);
                bh8   = lds32(bh_base + bo + 64);
#pragma unroll
                for (int mt = 0; mt < 2; mt++) {
                    float* c = acc[mt][nt];
                    mma16(c, ah[mt], bh);
                    mma8(c, ah[mt] + 4, bh8);
                }
            }
        }

        if (s + 1 < 32) {
            build_xh(sh, 2 * (s + 1), buf ^ 1, tid);
            asm volatile("cp.async.wait_group 0;" ::: "memory");
            __syncthreads();            // publish next stage xh + A
        }
    }

    // ---------------- epilogue: accs -> smem -> coalesced y + stats ---------
    __syncthreads();   // done reading xs/A/xh; reuse smem as sh_y[128][132]
#pragma unroll
    for (int mt = 0; mt < 2; mt++)
#pragma unroll
        for (int nt = 0; nt < 8; nt++) {
            int R0 = wr * 32 + mt * 16 + (l >> 2);
            int Cc = wc * 64 + nt * 8 + 2 * (l & 3);
            *(float2*)&sh[R0 * 132 + Cc]       = make_float2(acc[mt][nt][0], acc[mt][nt][1]);
            *(float2*)&sh[(R0 + 8) * 132 + Cc] = make_float2(acc[mt][nt][2], acc[mt][nt][3]);
        }
    __syncthreads();

    const bool fullt = (t0 + TN <= TC_);
#pragma unroll 1
    for (int it = 0; it < 16; ++it) {
        int row = it * 8 + wid;            // 0..127 = br*64+co
        int colb = l * 4;
        float4 v = *(float4*)&sh[row * 132 + colb];
        float s = 0.f, ss = 0.f;
        if (fullt) {
            s  = v.x + v.y + v.z + v.w;
            ss = v.x * v.x + v.y * v.y + v.z * v.z + v.w * v.w;
        } else {
#pragma unroll
            for (int e = 0; e < 4; e++) {
                if (t0 + colb + e < TC_) {
                    float f = (&v.x)[e];
                    s += f; ss += f * f;
                }
            }
        }
#pragma unroll
        for (int o = 16; o; o >>= 1) {
            s  += __shfl_xor_sync(0xffffffffu, s, o);
            ss += __shfl_xor_sync(0xffffffffu, ss, o);
        }
        if (l == 0) { atomicAdd(&g_sum[row], s); atomicAdd(&g_sumsq[row], ss); }
        int br = row >> 6, co = row & 63;
        float* yp = g_y + ((size_t)((br * B_ + b) * C_ + co)) * TP_ + t0;
        if (fullt) {
            *(float4*)&yp[colb] = v;
        } else {
#pragma unroll
            for (int e = 0; e < 4; e++)
                if (t0 + colb + e < TC_) yp[colb + e] = (&v.x)[e];
        }
    }
}

// ---------------- kernel 3: finalize BN affine ------------------------------
__global__ void finalize_kernel(const float* __restrict__ g1, const float* __restrict__ b1,
                                const float* __restrict__ g2, const float* __restrict__ b2) {
    int i = threadIdx.x;
    if (i < 2 * C_) {
        int br = i >> 6, c = i & 63;
        const float Nf = (float)(B_ * TC_);
        float mean = g_sum[i] / Nf;
        float var  = g_sumsq[i] / Nf - mean * mean;
        float gamma = br ? g2[c] : g1[c];
        float beta  = br ? b2[c] : b1[c];
        float a = gamma * rsqrtf(var + 1e-5f);
        g_scale[i] = a;
        g_shift[i] = beta - mean * a;
    }
}

// ---------------- kernel 4: SPP pooling -------------------------------------
__global__ __launch_bounds__(256) void pool_kernel(const int* __restrict__ orig_len) {
    const int co = blockIdx.x, b = blockIdx.y, br = blockIdx.z;
    const int L    = orig_len[b] - (K_ - 1);
    const int str  = L >> 1;
    const int kern = L - str;
    const float a  = g_scale[br * C_ + co];
    const float c0 = g_shift[br * C_ + co];
    const float* yp = g_y + (size_t)((br * B_ + b) * C_ + co) * TP_;
    const int tid = threadIdx.x;
    const float NINF = __int_as_float(0xff800000);

    float r0, r1, r2;
    if (br == 0) {
        float m = NINF, m0 = NINF, m1 = NINF;
        for (int t = tid; t < L; t += 256) {
            float v = fmaf(yp[t], a, c0);
            v = (v > 0.f) ? v : NEG * v;
            m = fmaxf(m, v);
            if (t < kern)  m0 = fmaxf(m0, v);
            if (t >= str)  m1 = fmaxf(m1, v);
        }
        r0 = m; r1 = m0; r2 = m1;
    } else {
        float s = 0.f, s0 = 0.f, s1 = 0.f;
        for (int t = tid; t < L; t += 256) {
            float v = fmaf(yp[t], a, c0);
            v = (v > 0.f) ? v : NEG * v;
            s += v;
            if (t < kern)  s0 += v;
            if (t >= str)  s1 += v;
        }
        r0 = s; r1 = s0; r2 = s1;
    }

    __shared__ float sred[3][8];
    const int lane = tid & 31, wrp = tid >> 5;
    if (br == 0) {
#pragma unroll
        for (int o = 16; o; o >>= 1) {
            r0 = fmaxf(r0, __shfl_xor_sync(0xffffffffu, r0, o));
            r1 = fmaxf(r1, __shfl_xor_sync(0xffffffffu, r1, o));
            r2 = fmaxf(r2, __shfl_xor_sync(0xffffffffu, r2, o));
        }
    } else {
#pragma unroll
        for (int o = 16; o; o >>= 1) {
            r0 += __shfl_xor_sync(0xffffffffu, r0, o);
            r1 += __shfl_xor_sync(0xffffffffu, r1, o);
            r2 += __shfl_xor_sync(0xffffffffu, r2, o);
        }
    }
    if (lane == 0) { sred[0][wrp] = r0; sred[1][wrp] = r1; sred[2][wrp] = r2; }
    __syncthreads();
    if (tid == 0) {
        float a0 = sred[0][0], a1 = sred[1][0], a2 = sred[2][0];
        for (int w = 1; w < 8; w++) {
            if (br == 0) {
                a0 = fmaxf(a0, sred[0][w]);
                a1 = fmaxf(a1, sred[1][w]);
                a2 = fmaxf(a2, sred[2][w]);
            } else {
                a0 += sred[0][w]; a1 += sred[1][w]; a2 += sred[2][w];
            }
        }
        float* f = g_feat + b * 384;
        if (br == 0) {
            f[co] = a0;
            f[64 + 2 * co]     = a1;
            f[64 + 2 * co + 1] = a2;
        } else {
            f[192 + co] = a0 / (float)L;
            f[256 + 2 * co]     = a1 / (float)kern;
            f[256 + 2 * co + 1] = a2 / (float)kern;
        }
    }
}

// ---------------- kernel 5: FC head -----------------------------------------
__global__ void fc_kernel(const float* __restrict__ fcw, const float* __restrict__ fcb,
                          float* __restrict__ out) {
    int i = threadIdx.x;
    if (i < B_ * 2) {
        int b = i >> 1, t = i & 1;
        float acc = fcb[t];
        const float* f = g_feat + b * 384;
        const float* w = fcw + t * 384;
#pragma unroll 8
        for (int j = 0; j < 384; j++) acc += f[j] * w[j];
        out[i] = acc;
    }
}

// ---------------- launch ----------------------------------------------------
extern "C" void kernel_launch(void* const* d_in, const int* in_sizes, int n_in,
                              void* d_out, int out_size) {
    const float* x        = (const float*)d_in[0];
    const int*   orig_len = (const int*)  d_in[1];
    const float* w1       = (const float*)d_in[2];
    const float* g1       = (const float*)d_in[3];
    const float* b1       = (const float*)d_in[4];
    const float* w2       = (const float*)d_in[5];
    const float* g2       = (const float*)d_in[6];
    const float* b2       = (const float*)d_in[7];
    const float* fcw      = (const float*)d_in[8];
    const float* fcb      = (const float*)d_in[9];
    float* out = (float*)d_out;

    cudaFuncSetAttribute(conv_kernel, cudaFuncAttributeMaxDynamicSharedMemorySize,
                         SMEM_TOTAL);

    zero_kernel<<<1, 128>>>();
    wpack_kernel<<<(64 * 128 * KT + 255) / 256, 256>>>(w1, w2);
    pad_kernel<<<1, 32>>>();   // keeps the ncu -s window on conv
    conv_kernel<<<dim3(NTB, B_), 256, SMEM_TOTAL>>>(x);
    finalize_kernel<<<1, 128>>>(g1, b1, g2, b2);
    pool_kernel<<<dim3(C_, B_, 2), 256>>>(orig_len);
    fc_kernel<<<1, 64>>>(fcw, fcb, out);
}

// round 13
// speedup vs baseline: 1.0790x; 1.0372x over previous
#include <cuda_runtime.h>
#include <cuda_fp16.h>
#include <cstdint>
#include <cstddef>

#define B_ 32
#define C_ 64
#define T_ 16384
#define K_ 21
#define KT 24           // taps padded (A holds zeros for 21..23)
#define TC_ 16364       // T - (K-1)
#define TP_ 16384
#define NEG 0.01f

#define TN 128          // time per CTA
#define NTB 128         // ceil(TC_/TN)
#define XW 152          // staged x row width (floats)

// smem layout (bytes)
#define XH_OFF 0
#define XH_BUF 624                      // 156 half2 per ci
#define XH_TOT (64*XH_BUF)              // 39936 (all 64 ci resident)
#define A_OFF  XH_TOT                   // 39936
#define A_CI   6144                     // 128 rows * 24 taps * 2B
#define CPS    4                        // ci per pipeline stage
#define A_STG  (CPS*A_CI)               // 24576
#define NSTG   16
#define XS_OFF A_OFF                    // fp32 x tile overlays A ring (init only)
#define SMEM_TOTAL (A_OFF + 2*A_STG)    // 89088; epilogue y (67584) fits at 0

// ---------------- device scratch --------------------------------------------
__device__ float g_y[(size_t)2 * B_ * C_ * TP_];            // [br][b][co][t]
__device__ __align__(16) __half g_wA[64 * 128 * KT];        // [ci][m][kk] (fp16)
__device__ float g_sum[2 * C_], g_sumsq[2 * C_];
__device__ float g_scale[2 * C_], g_shift[2 * C_];
__device__ float g_feat[B_ * 384];

// ---------------- PTX helpers -----------------------------------------------
__device__ __forceinline__ uint32_t smem_u32(const void* p) {
    uint32_t a;
    asm("{ .reg .u64 t; cvta.to.shared.u64 t, %1; cvt.u32.u64 %0, t; }"
        : "=r"(a) : "l"(p));
    return a;
}
__device__ __forceinline__ void ldsm4(uint32_t* r, uint32_t addr) {
    asm volatile("ldmatrix.sync.aligned.m8n8.x4.shared.b16 {%0,%1,%2,%3}, [%4];"
        : "=r"(r[0]), "=r"(r[1]), "=r"(r[2]), "=r"(r[3]) : "r"(addr));
}
__device__ __forceinline__ void ldsm2(uint32_t* r, uint32_t addr) {
    asm volatile("ldmatrix.sync.aligned.m8n8.x2.shared.b16 {%0,%1}, [%2];"
        : "=r"(r[0]), "=r"(r[1]) : "r"(addr));
}
__device__ __forceinline__ uint32_t lds32(uint32_t addr) {
    uint32_t v;
    asm volatile("ld.shared.b32 %0, [%1];" : "=r"(v) : "r"(addr));
    return v;
}
__device__ __forceinline__ void mma16(float* c, const uint32_t* a, const uint32_t* b) {
    asm volatile("mma.sync.aligned.m16n8k16.row.col.f32.f16.f16.f32 "
        "{%0,%1,%2,%3}, {%4,%5,%6,%7}, {%8,%9}, {%0,%1,%2,%3};"
        : "+f"(c[0]), "+f"(c[1]), "+f"(c[2]), "+f"(c[3])
        : "r"(a[0]), "r"(a[1]), "r"(a[2]), "r"(a[3]), "r"(b[0]), "r"(b[1]));
}
__device__ __forceinline__ void mma8(float* c, const uint32_t* a, uint32_t b) {
    asm volatile("mma.sync.aligned.m16n8k8.row.col.f32.f16.f16.f32 "
        "{%0,%1,%2,%3}, {%4,%5}, {%6}, {%0,%1,%2,%3};"
        : "+f"(c[0]), "+f"(c[1]), "+f"(c[2]), "+f"(c[3])
        : "r"(a[0]), "r"(a[1]), "r"(b));
}
__device__ __forceinline__ void cpasync16(uint32_t dst, const void* src) {
    asm volatile("cp.async.cg.shared.global [%0], [%1], 16;" :: "r"(dst), "l"(src));
}

// ---------------- kernel 0: zero stats --------------------------------------
__global__ void zero_kernel() {
    int i = threadIdx.x;
    if (i < 2 * C_) { g_sum[i] = 0.f; g_sumsq[i] = 0.f; }
}

// ---------------- kernel 1: weight prep (fp16, tap-padded) ------------------
__global__ void wpack_kernel(const float* __restrict__ w1,
                             const float* __restrict__ w2) {
    int idx = blockIdx.x * blockDim.x + threadIdx.x;
    if (idx >= 64 * 128 * KT) return;
    int ci = idx / (128 * KT);
    int r2 = idx % (128 * KT);
    int m  = r2 / KT;
    int kk = r2 % KT;
    float v = 0.f;
    if (kk < K_)
        v = (m < 64) ? w1[(m * 64 + ci) * K_ + kk]
                     : w2[((m - 64) * 64 + ci) * K_ + kk];
    g_wA[idx] = __float2half_rn(v);
}

// ---------------- pad kernel (ncu -s slot alignment) ------------------------
__global__ void pad_kernel() {}

// ---------------- A-stage prefetch -------------------------------------------
__device__ __forceinline__ void prefetch_A(uint32_t sbase, int stg, int buf,
                                           int tid) {
    const char* src = (const char*)g_wA + (size_t)stg * A_STG;
    uint32_t dst = sbase + A_OFF + buf * A_STG;
    for (int c = tid; c < A_STG / 16; c += 256)     // 1536 chunks
        cpasync16(dst + c * 16, src + c * 16);
    asm volatile("cp.async.commit_group;" ::: "memory");
}

// ---------------- kernel 2: conv via mma.sync fp16 implicit GEMM ------------
// xh for all 64 ci built once; mainloop = pure A-prefetch + MMA, 16 barriers
__global__ __launch_bounds__(256, 2) void conv_kernel(const float* __restrict__ x) {
    extern __shared__ float sh[];
    const int b   = blockIdx.y;
    const int t0  = blockIdx.x * TN;
    const int tid = threadIdx.x;
    const int wid = tid >> 5;
    const int l   = tid & 31;
    const uint32_t sbase = smem_u32(sh);

    // stage fp32 x tile into the (future) A-ring region
    float* xs = (float*)((char*)sh + XS_OFF);
    for (int i = tid; i < 64 * (XW / 4); i += 256) {
        int ci = i / (XW / 4), j4 = i % (XW / 4);
        int gt = t0 + j4 * 4;
        float4 v = make_float4(0.f, 0.f, 0.f, 0.f);
        if (gt + 3 < T_) v = *(const float4*)&x[((size_t)b * C_ + ci) * T_ + gt];
        else {
            for (int e = 0; e < 4; e++)
                if (gt + e < T_) (&v.x)[e] = x[((size_t)b * C_ + ci) * T_ + gt + e];
        }
        *(float4*)&xs[ci * XW + j4 * 4] = v;
    }
    __syncthreads();

    // build ALL xh (fp16 sliding-window pairs) once
    for (int i = tid; i < 64 * 152; i += 256) {
        int ci = i / 152, j = i - ci * 152;
        float v0 = xs[ci * XW + j];
        float v1 = (j + 1 < 152) ? xs[ci * XW + j + 1] : 0.f;
        __half2* xh2 = (__half2*)((char*)sh + XH_OFF + ci * XH_BUF);
        xh2[j] = __halves2half2(__float2half_rn(v0), __float2half_rn(v1));
    }
    __syncthreads();            // xs dead beyond this point

    prefetch_A(sbase, 0, 0, tid);
    asm volatile("cp.async.wait_group 0;" ::: "memory");
    __syncthreads();

    const int wr = wid >> 1;          // 0..3 (M)
    const int wc = wid & 1;           // 0..1 (N)
    float acc[2][8][4];
#pragma unroll
    for (int mt = 0; mt < 2; mt++)
#pragma unroll
        for (int nt = 0; nt < 8; nt++)
#pragma unroll
            for (int e = 0; e < 4; e++) acc[mt][nt][e] = 0.f;

    const uint32_t blane = 4 * (wc * 64 + (l >> 2) + 2 * (l & 3));

    for (int s = 0; s < NSTG; ++s) {
        const int buf = s & 1;
        if (s + 1 < NSTG) prefetch_A(sbase, s + 1, buf ^ 1, tid);

#pragma unroll
        for (int cc = 0; cc < CPS; ++cc) {
            const int ci = s * CPS + cc;
            const uint32_t abase = sbase + A_OFF + buf * A_STG + cc * A_CI;
            uint32_t ah[2][6];
#pragma unroll
            for (int mt = 0; mt < 2; mt++) {
                int row = wr * 32 + mt * 16 + (l & 15);
                uint32_t a16 = abase + row * 48 + (l >> 4) * 16;
                uint32_t a8  = abase + row * 48 + 32;
                ldsm4(ah[mt], a16);
                ldsm2(ah[mt] + 4, a8);
            }
            const uint32_t bh_base = sbase + XH_OFF + ci * XH_BUF + blane;
#pragma unroll
            for (int nt = 0; nt < 8; nt++) {
                uint32_t bo = nt * 32;
                uint32_t bh[2], bh8;
                bh[0] = lds32(bh_base + bo);
                bh[1] = lds32(bh_base + bo + 32);
                bh8   = lds32(bh_base + bo + 64);
#pragma unroll
                for (int mt = 0; mt < 2; mt++) {
                    float* c = acc[mt][nt];
                    mma16(c, ah[mt], bh);
                    mma8(c, ah[mt] + 4, bh8);
                }
            }
        }

        if (s + 1 < NSTG) {
            asm volatile("cp.async.wait_group 0;" ::: "memory");
            __syncthreads();            // A(s+1) ready; buffer s reusable
        }
    }

    // ---------------- epilogue: accs -> smem -> coalesced y + stats ---------
    __syncthreads();   // done reading xh/A; reuse smem as sh_y[128][132]
#pragma unroll
    for (int mt = 0; mt < 2; mt++)
#pragma unroll
        for (int nt = 0; nt < 8; nt++) {
            int R0 = wr * 32 + mt * 16 + (l >> 2);
            int Cc = wc * 64 + nt * 8 + 2 * (l & 3);
            *(float2*)&sh[R0 * 132 + Cc]       = make_float2(acc[mt][nt][0], acc[mt][nt][1]);
            *(float2*)&sh[(R0 + 8) * 132 + Cc] = make_float2(acc[mt][nt][2], acc[mt][nt][3]);
        }
    __syncthreads();

    const bool fullt = (t0 + TN <= TC_);
#pragma unroll 1
    for (int it = 0; it < 16; ++it) {
        int row = it * 8 + wid;            // 0..127 = br*64+co
        int colb = l * 4;
        float4 v = *(float4*)&sh[row * 132 + colb];
        float s = 0.f, ss = 0.f;
        if (fullt) {
            s  = v.x + v.y + v.z + v.w;
            ss = v.x * v.x + v.y * v.y + v.z * v.z + v.w * v.w;
        } else {
#pragma unroll
            for (int e = 0; e < 4; e++) {
                if (t0 + colb + e < TC_) {
                    float f = (&v.x)[e];
                    s += f; ss += f * f;
                }
            }
        }
#pragma unroll
        for (int o = 16; o; o >>= 1) {
            s  += __shfl_xor_sync(0xffffffffu, s, o);
            ss += __shfl_xor_sync(0xffffffffu, ss, o);
        }
        if (l == 0) { atomicAdd(&g_sum[row], s); atomicAdd(&g_sumsq[row], ss); }
        int br = row >> 6, co = row & 63;
        float* yp = g_y + ((size_t)((br * B_ + b) * C_ + co)) * TP_ + t0;
        if (fullt) {
            *(float4*)&yp[colb] = v;
        } else {
#pragma unroll
            for (int e = 0; e < 4; e++)
                if (t0 + colb + e < TC_) yp[colb + e] = (&v.x)[e];
        }
    }
}

// ---------------- kernel 3: finalize BN affine ------------------------------
__global__ void finalize_kernel(const float* __restrict__ g1, const float* __restrict__ b1,
                                const float* __restrict__ g2, const float* __restrict__ b2) {
    int i = threadIdx.x;
    if (i < 2 * C_) {
        int br = i >> 6, c = i & 63;
        const float Nf = (float)(B_ * TC_);
        float mean = g_sum[i] / Nf;
        float var  = g_sumsq[i] / Nf - mean * mean;
        float gamma = br ? g2[c] : g1[c];
        float beta  = br ? b2[c] : b1[c];
        float a = gamma * rsqrtf(var + 1e-5f);
        g_scale[i] = a;
        g_shift[i] = beta - mean * a;
    }
}

// ---------------- kernel 4: SPP pooling -------------------------------------
__global__ __launch_bounds__(256) void pool_kernel(const int* __restrict__ orig_len) {
    const int co = blockIdx.x, b = blockIdx.y, br = blockIdx.z;
    const int L    = orig_len[b] - (K_ - 1);
    const int str  = L >> 1;
    const int kern = L - str;
    const float a  = g_scale[br * C_ + co];
    const float c0 = g_shift[br * C_ + co];
    const float* yp = g_y + (size_t)((br * B_ + b) * C_ + co) * TP_;
    const int tid = threadIdx.x;
    const float NINF = __int_as_float(0xff800000);

    float r0, r1, r2;
    if (br == 0) {
        float m = NINF, m0 = NINF, m1 = NINF;
        for (int t = tid; t < L; t += 256) {
            float v = fmaf(yp[t], a, c0);
            v = (v > 0.f) ? v : NEG * v;
            m = fmaxf(m, v);
            if (t < kern)  m0 = fmaxf(m0, v);
            if (t >= str)  m1 = fmaxf(m1, v);
        }
        r0 = m; r1 = m0; r2 = m1;
    } else {
        float s = 0.f, s0 = 0.f, s1 = 0.f;
        for (int t = tid; t < L; t += 256) {
            float v = fmaf(yp[t], a, c0);
            v = (v > 0.f) ? v : NEG * v;
            s += v;
            if (t < kern)  s0 += v;
            if (t >= str)  s1 += v;
        }
        r0 = s; r1 = s0; r2 = s1;
    }

    __shared__ float sred[3][8];
    const int lane = tid & 31, wrp = tid >> 5;
    if (br == 0) {
#pragma unroll
        for (int o = 16; o; o >>= 1) {
            r0 = fmaxf(r0, __shfl_xor_sync(0xffffffffu, r0, o));
            r1 = fmaxf(r1, __shfl_xor_sync(0xffffffffu, r1, o));
            r2 = fmaxf(r2, __shfl_xor_sync(0xffffffffu, r2, o));
        }
    } else {
#pragma unroll
        for (int o = 16; o; o >>= 1) {
            r0 += __shfl_xor_sync(0xffffffffu, r0, o);
            r1 += __shfl_xor_sync(0xffffffffu, r1, o);
            r2 += __shfl_xor_sync(0xffffffffu, r2, o);
        }
    }
    if (lane == 0) { sred[0][wrp] = r0; sred[1][wrp] = r1; sred[2][wrp] = r2; }
    __syncthreads();
    if (tid == 0) {
        float a0 = sred[0][0], a1 = sred[1][0], a2 = sred[2][0];
        for (int w = 1; w < 8; w++) {
            if (br == 0) {
                a0 = fmaxf(a0, sred[0][w]);
                a1 = fmaxf(a1, sred[1][w]);
                a2 = fmaxf(a2, sred[2][w]);
            } else {
                a0 += sred[0][w]; a1 += sred[1][w]; a2 += sred[2][w];
            }
        }
        float* f = g_feat + b * 384;
        if (br == 0) {
            f[co] = a0;
            f[64 + 2 * co]     = a1;
            f[64 + 2 * co + 1] = a2;
        } else {
            f[192 + co] = a0 / (float)L;
            f[256 + 2 * co]     = a1 / (float)kern;
            f[256 + 2 * co + 1] = a2 / (float)kern;
        }
    }
}

// ---------------- kernel 5: FC head -----------------------------------------
__global__ void fc_kernel(const float* __restrict__ fcw, const float* __restrict__ fcb,
                          float* __restrict__ out) {
    int i = threadIdx.x;
    if (i < B_ * 2) {
        int b = i >> 1, t = i & 1;
        float acc = fcb[t];
        const float* f = g_feat + b * 384;
        const float* w = fcw + t * 384;
#pragma unroll 8
        for (int j = 0; j < 384; j++) acc += f[j] * w[j];
        out[i] = acc;
    }
}

// ---------------- launch ----------------------------------------------------
extern "C" void kernel_launch(void* const* d_in, const int* in_sizes, int n_in,
                              void* d_out, int out_size) {
    const float* x        = (const float*)d_in[0];
    const int*   orig_len = (const int*)  d_in[1];
    const float* w1       = (const float*)d_in[2];
    const float* g1       = (const float*)d_in[3];
    const float* b1       = (const float*)d_in[4];
    const float* w2       = (const float*)d_in[5];
    const float* g2       = (const float*)d_in[6];
    const float* b2       = (const float*)d_in[7];
    const float* fcw      = (const float*)d_in[8];
    const float* fcb      = (const float*)d_in[9];
    float* out = (float*)d_out;

    cudaFuncSetAttribute(conv_kernel, cudaFuncAttributeMaxDynamicSharedMemorySize,
                         SMEM_TOTAL);

    zero_kernel<<<1, 128>>>();
    wpack_kernel<<<(64 * 128 * KT + 255) / 256, 256>>>(w1, w2);
    pad_kernel<<<1, 32>>>();   // keeps the ncu -s window on conv
    conv_kernel<<<dim3(NTB, B_), 256, SMEM_TOTAL>>>(x);
    finalize_kernel<<<1, 128>>>(g1, b1, g2, b2);
    pool_kernel<<<dim3(C_, B_, 2), 256>>>(orig_len);
    fc_kernel<<<1, 64>>>(fcw, fcb, out);
}

// round 14
// speedup vs baseline: 1.0796x; 1.0006x over previous
#include <cuda_runtime.h>
#include <cuda_fp16.h>
#include <cstdint>
#include <cstddef>

#define B_ 32
#define C_ 64
#define T_ 16384
#define K_ 21
#define KT 24           // taps padded (A holds zeros for 21..23)
#define TC_ 16364       // T - (K-1)
#define TP_ 16384
#define NEG 0.01f

#define TN 128          // time per CTA
#define NTB 128         // ceil(TC_/TN)
#define XW 152          // staged x row width (floats)

// smem layout (bytes)
#define XH_OFF 0
#define XH_BUF 624                      // 156 half2 per ci
#define XH_TOT (64*XH_BUF)              // 39936 (all 64 ci resident)
#define A_OFF  XH_TOT                   // 39936
#define A_CI   6144                     // 128 rows * 24 taps * 2B
#define CPS    4                        // ci per pipeline stage
#define A_STG  (CPS*A_CI)               // 24576
#define NSTG   16
#define XS_OFF A_OFF                    // fp32 x tile overlays A ring (init only)
#define SMEM_TOTAL (A_OFF + 2*A_STG)    // 89088; epilogue y (67584) fits at 0

// ---------------- device scratch --------------------------------------------
__device__ float g_y[(size_t)2 * B_ * C_ * TP_];            // [br][b][co][t]
__device__ __align__(16) __half g_wA[64 * 128 * KT];        // [ci][m][kk] (fp16)
__device__ float g_sum[2 * C_], g_sumsq[2 * C_];
__device__ float g_scale[2 * C_], g_shift[2 * C_];
__device__ float g_feat[B_ * 384];

// ---------------- PTX helpers -----------------------------------------------
__device__ __forceinline__ uint32_t smem_u32(const void* p) {
    uint32_t a;
    asm("{ .reg .u64 t; cvta.to.shared.u64 t, %1; cvt.u32.u64 %0, t; }"
        : "=r"(a) : "l"(p));
    return a;
}
__device__ __forceinline__ void ldsm4(uint32_t* r, uint32_t addr) {
    asm volatile("ldmatrix.sync.aligned.m8n8.x4.shared.b16 {%0,%1,%2,%3}, [%4];"
        : "=r"(r[0]), "=r"(r[1]), "=r"(r[2]), "=r"(r[3]) : "r"(addr));
}
__device__ __forceinline__ void ldsm2(uint32_t* r, uint32_t addr) {
    asm volatile("ldmatrix.sync.aligned.m8n8.x2.shared.b16 {%0,%1}, [%2];"
        : "=r"(r[0]), "=r"(r[1]) : "r"(addr));
}
__device__ __forceinline__ uint32_t lds32(uint32_t addr) {
    uint32_t v;
    asm volatile("ld.shared.b32 %0, [%1];" : "=r"(v) : "r"(addr));
    return v;
}
__device__ __forceinline__ void mma16(float* c, const uint32_t* a, const uint32_t* b) {
    asm volatile("mma.sync.aligned.m16n8k16.row.col.f32.f16.f16.f32 "
        "{%0,%1,%2,%3}, {%4,%5,%6,%7}, {%8,%9}, {%0,%1,%2,%3};"
        : "+f"(c[0]), "+f"(c[1]), "+f"(c[2]), "+f"(c[3])
        : "r"(a[0]), "r"(a[1]), "r"(a[2]), "r"(a[3]), "r"(b[0]), "r"(b[1]));
}
__device__ __forceinline__ void mma8(float* c, const uint32_t* a, uint32_t b) {
    asm volatile("mma.sync.aligned.m16n8k8.row.col.f32.f16.f16.f32 "
        "{%0,%1,%2,%3}, {%4,%5}, {%6}, {%0,%1,%2,%3};"
        : "+f"(c[0]), "+f"(c[1]), "+f"(c[2]), "+f"(c[3])
        : "r"(a[0]), "r"(a[1]), "r"(b));
}
__device__ __forceinline__ void cpasync16(uint32_t dst, const void* src) {
    asm volatile("cp.async.cg.shared.global [%0], [%1], 16;" :: "r"(dst), "l"(src));
}

// ---------------- kernel 0: zero stats --------------------------------------
__global__ void zero_kernel() {
    int i = threadIdx.x;
    if (i < 2 * C_) { g_sum[i] = 0.f; g_sumsq[i] = 0.f; }
}

// ---------------- kernel 1: weight prep (fp16, tap-padded) ------------------
__global__ void wpack_kernel(const float* __restrict__ w1,
                             const float* __restrict__ w2) {
    int idx = blockIdx.x * blockDim.x + threadIdx.x;
    if (idx >= 64 * 128 * KT) return;
    int ci = idx / (128 * KT);
    int r2 = idx % (128 * KT);
    int m  = r2 / KT;
    int kk = r2 % KT;
    float v = 0.f;
    if (kk < K_)
        v = (m < 64) ? w1[(m * 64 + ci) * K_ + kk]
                     : w2[((m - 64) * 64 + ci) * K_ + kk];
    g_wA[idx] = __float2half_rn(v);
}

// ---------------- pad kernel (ncu -s slot alignment) ------------------------
__global__ void pad_kernel() {}

// ---------------- A-stage prefetch -------------------------------------------
__device__ __forceinline__ void prefetch_A(uint32_t sbase, int stg, int buf,
                                           int tid) {
    const char* src = (const char*)g_wA + (size_t)stg * A_STG;
    uint32_t dst = sbase + A_OFF + buf * A_STG;
    for (int c = tid; c < A_STG / 16; c += 256)     // 1536 chunks
        cpasync16(dst + c * 16, src + c * 16);
    asm volatile("cp.async.commit_group;" ::: "memory");
}

// ---------------- kernel 2: conv via mma.sync fp16 implicit GEMM ------------
// xh for all 64 ci built once; mainloop = pure A-prefetch + MMA, 16 barriers
__global__ __launch_bounds__(256, 2) void conv_kernel(const float* __restrict__ x) {
    extern __shared__ float sh[];
    const int b   = blockIdx.y;
    const int t0  = blockIdx.x * TN;
    const int tid = threadIdx.x;
    const int wid = tid >> 5;
    const int l   = tid & 31;
    const uint32_t sbase = smem_u32(sh);

    // stage fp32 x tile into the (future) A-ring region
    float* xs = (float*)((char*)sh + XS_OFF);
    for (int i = tid; i < 64 * (XW / 4); i += 256) {
        int ci = i / (XW / 4), j4 = i % (XW / 4);
        int gt = t0 + j4 * 4;
        float4 v = make_float4(0.f, 0.f, 0.f, 0.f);
        if (gt + 3 < T_) v = *(const float4*)&x[((size_t)b * C_ + ci) * T_ + gt];
        else {
            for (int e = 0; e < 4; e++)
                if (gt + e < T_) (&v.x)[e] = x[((size_t)b * C_ + ci) * T_ + gt + e];
        }
        *(float4*)&xs[ci * XW + j4 * 4] = v;
    }
    __syncthreads();

    // build ALL xh (fp16 sliding-window pairs) once
    for (int i = tid; i < 64 * 152; i += 256) {
        int ci = i / 152, j = i - ci * 152;
        float v0 = xs[ci * XW + j];
        float v1 = (j + 1 < 152) ? xs[ci * XW + j + 1] : 0.f;
        __half2* xh2 = (__half2*)((char*)sh + XH_OFF + ci * XH_BUF);
        xh2[j] = __halves2half2(__float2half_rn(v0), __float2half_rn(v1));
    }
    __syncthreads();            // xs dead beyond this point

    prefetch_A(sbase, 0, 0, tid);
    asm volatile("cp.async.wait_group 0;" ::: "memory");
    __syncthreads();

    const int wr = wid >> 1;          // 0..3 (M)
    const int wc = wid & 1;           // 0..1 (N)
    float acc[2][8][4];
#pragma unroll
    for (int mt = 0; mt < 2; mt++)
#pragma unroll
        for (int nt = 0; nt < 8; nt++)
#pragma unroll
            for (int e = 0; e < 4; e++) acc[mt][nt][e] = 0.f;

    const uint32_t blane = 4 * (wc * 64 + (l >> 2) + 2 * (l & 3));

    for (int s = 0; s < NSTG; ++s) {
        const int buf = s & 1;
        if (s + 1 < NSTG) prefetch_A(sbase, s + 1, buf ^ 1, tid);

#pragma unroll
        for (int cc = 0; cc < CPS; ++cc) {
            const int ci = s * CPS + cc;
            const uint32_t abase = sbase + A_OFF + buf * A_STG + cc * A_CI;
            uint32_t ah[2][6];
#pragma unroll
            for (int mt = 0; mt < 2; mt++) {
                int row = wr * 32 + mt * 16 + (l & 15);
                uint32_t a16 = abase + row * 48 + (l >> 4) * 16;
                uint32_t a8  = abase + row * 48 + 32;
                ldsm4(ah[mt], a16);
                ldsm2(ah[mt] + 4, a8);
            }
            const uint32_t bh_base = sbase + XH_OFF + ci * XH_BUF + blane;
#pragma unroll
            for (int nt = 0; nt < 8; nt++) {
                uint32_t bo = nt * 32;
                uint32_t bh[2], bh8;
                bh[0] = lds32(bh_base + bo);
                bh[1] = lds32(bh_base + bo + 32);
                bh8   = lds32(bh_base + bo + 64);
#pragma unroll
                for (int mt = 0; mt < 2; mt++) {
                    float* c = acc[mt][nt];
                    mma16(c, ah[mt], bh);
                    mma8(c, ah[mt] + 4, bh8);
                }
            }
        }

        if (s + 1 < NSTG) {
            asm volatile("cp.async.wait_group 0;" ::: "memory");
            __syncthreads();            // A(s+1) ready; buffer s reusable
        }
    }

    // ---------------- epilogue: accs -> smem -> coalesced y + stats ---------
    __syncthreads();   // done reading xh/A; reuse smem as sh_y[128][132]
#pragma unroll
    for (int mt = 0; mt < 2; mt++)
#pragma unroll
        for (int nt = 0; nt < 8; nt++) {
            int R0 = wr * 32 + mt * 16 + (l >> 2);
            int Cc = wc * 64 + nt * 8 + 2 * (l & 3);
            *(float2*)&sh[R0 * 132 + Cc]       = make_float2(acc[mt][nt][0], acc[mt][nt][1]);
            *(float2*)&sh[(R0 + 8) * 132 + Cc] = make_float2(acc[mt][nt][2], acc[mt][nt][3]);
        }
    __syncthreads();

    const bool fullt = (t0 + TN <= TC_);
#pragma unroll 1
    for (int it = 0; it < 16; ++it) {
        int row = it * 8 + wid;            // 0..127 = br*64+co
        int colb = l * 4;
        float4 v = *(float4*)&sh[row * 132 + colb];
        float s = 0.f, ss = 0.f;
        if (fullt) {
            s  = v.x + v.y + v.z + v.w;
            ss = v.x * v.x + v.y * v.y + v.z * v.z + v.w * v.w;
        } else {
#pragma unroll
            for (int e = 0; e < 4; e++) {
                if (t0 + colb + e < TC_) {
                    float f = (&v.x)[e];
                    s += f; ss += f * f;
                }
            }
        }
#pragma unroll
        for (int o = 16; o; o >>= 1) {
            s  += __shfl_xor_sync(0xffffffffu, s, o);
            ss += __shfl_xor_sync(0xffffffffu, ss, o);
        }
        if (l == 0) { atomicAdd(&g_sum[row], s); atomicAdd(&g_sumsq[row], ss); }
        int br = row >> 6, co = row & 63;
        float* yp = g_y + ((size_t)((br * B_ + b) * C_ + co)) * TP_ + t0;
        if (fullt) {
            *(float4*)&yp[colb] = v;
        } else {
#pragma unroll
            for (int e = 0; e < 4; e++)
                if (t0 + colb + e < TC_) yp[colb + e] = (&v.x)[e];
        }
    }
}

// ---------------- kernel 3: finalize BN affine ------------------------------
__global__ void finalize_kernel(const float* __restrict__ g1, const float* __restrict__ b1,
                                const float* __restrict__ g2, const float* __restrict__ b2) {
    int i = threadIdx.x;
    if (i < 2 * C_) {
        int br = i >> 6, c = i & 63;
        const float Nf = (float)(B_ * TC_);
        float mean = g_sum[i] / Nf;
        float var  = g_sumsq[i] / Nf - mean * mean;
        float gamma = br ? g2[c] : g1[c];
        float beta  = br ? b2[c] : b1[c];
        float a = gamma * rsqrtf(var + 1e-5f);
        g_scale[i] = a;
        g_shift[i] = beta - mean * a;
    }
}

// ---------------- kernel 4: SPP pooling -------------------------------------
__global__ __launch_bounds__(256) void pool_kernel(const int* __restrict__ orig_len) {
    const int co = blockIdx.x, b = blockIdx.y, br = blockIdx.z;
    const int L    = orig_len[b] - (K_ - 1);
    const int str  = L >> 1;
    const int kern = L - str;
    const float a  = g_scale[br * C_ + co];
    const float c0 = g_shift[br * C_ + co];
    const float* yp = g_y + (size_t)((br * B_ + b) * C_ + co) * TP_;
    const int tid = threadIdx.x;
    const float NINF = __int_as_float(0xff800000);

    float r0, r1, r2;
    if (br == 0) {
        float m = NINF, m0 = NINF, m1 = NINF;
        for (int t = tid; t < L; t += 256) {
            float v = fmaf(yp[t], a, c0);
            v = (v > 0.f) ? v : NEG * v;
            m = fmaxf(m, v);
            if (t < kern)  m0 = fmaxf(m0, v);
            if (t >= str)  m1 = fmaxf(m1, v);
        }
        r0 = m; r1 = m0; r2 = m1;
    } else {
        float s = 0.f, s0 = 0.f, s1 = 0.f;
        for (int t = tid; t < L; t += 256) {
            float v = fmaf(yp[t], a, c0);
            v = (v > 0.f) ? v : NEG * v;
            s += v;
            if (t < kern)  s0 += v;
            if (t >= str)  s1 += v;
        }
        r0 = s; r1 = s0; r2 = s1;
    }

    __shared__ float sred[3][8];
    const int lane = tid & 31, wrp = tid >> 5;
    if (br == 0) {
#pragma unroll
        for (int o = 16; o; o >>= 1) {
            r0 = fmaxf(r0, __shfl_xor_sync(0xffffffffu, r0, o));
            r1 = fmaxf(r1, __shfl_xor_sync(0xffffffffu, r1, o));
            r2 = fmaxf(r2, __shfl_xor_sync(0xffffffffu, r2, o));
        }
    } else {
#pragma unroll
        for (int o = 16; o; o >>= 1) {
            r0 += __shfl_xor_sync(0xffffffffu, r0, o);
            r1 += __shfl_xor_sync(0xffffffffu, r1, o);
            r2 += __shfl_xor_sync(0xffffffffu, r2, o);
        }
    }
    if (lane == 0) { sred[0][wrp] = r0; sred[1][wrp] = r1; sred[2][wrp] = r2; }
    __syncthreads();
    if (tid == 0) {
        float a0 = sred[0][0], a1 = sred[1][0], a2 = sred[2][0];
        for (int w = 1; w < 8; w++) {
            if (br == 0) {
                a0 = fmaxf(a0, sred[0][w]);
                a1 = fmaxf(a1, sred[1][w]);
                a2 = fmaxf(a2, sred[2][w]);
            } else {
                a0 += sred[0][w]; a1 += sred[1][w]; a2 += sred[2][w];
            }
        }
        float* f = g_feat + b * 384;
        if (br == 0) {
            f[co] = a0;
            f[64 + 2 * co]     = a1;
            f[64 + 2 * co + 1] = a2;
        } else {
            f[192 + co] = a0 / (float)L;
            f[256 + 2 * co]     = a1 / (float)kern;
            f[256 + 2 * co + 1] = a2 / (float)kern;
        }
    }
}

// ---------------- kernel 5: FC head -----------------------------------------
__global__ void fc_kernel(const float* __restrict__ fcw, const float* __restrict__ fcb,
                          float* __restrict__ out) {
    int i = threadIdx.x;
    if (i < B_ * 2) {
        int b = i >> 1, t = i & 1;
        float acc = fcb[t];
        const float* f = g_feat + b * 384;
        const float* w = fcw + t * 384;
#pragma unroll 8
        for (int j = 0; j < 384; j++) acc += f[j] * w[j];
        out[i] = acc;
    }
}

// ---------------- launch ----------------------------------------------------
extern "C" void kernel_launch(void* const* d_in, const int* in_sizes, int n_in,
                              void* d_out, int out_size) {
    const float* x        = (const float*)d_in[0];
    const int*   orig_len = (const int*)  d_in[1];
    const float* w1       = (const float*)d_in[2];
    const float* g1       = (const float*)d_in[3];
    const float* b1       = (const float*)d_in[4];
    const float* w2       = (const float*)d_in[5];
    const float* g2       = (const float*)d_in[6];
    const float* b2       = (const float*)d_in[7];
    const float* fcw      = (const float*)d_in[8];
    const float* fcb      = (const float*)d_in[9];
    float* out = (float*)d_out;

    cudaFuncSetAttribute(conv_kernel, cudaFuncAttributeMaxDynamicSharedMemorySize,
                         SMEM_TOTAL);

    zero_kernel<<<1, 128>>>();
    wpack_kernel<<<(64 * 128 * KT + 255) / 256, 256>>>(w1, w2);
    pad_kernel<<<1, 32>>>();   // keeps the ncu -s window on conv
    conv_kernel<<<dim3(NTB, B_), 256, SMEM_TOTAL>>>(x);
    finalize_kernel<<<1, 128>>>(g1, b1, g2, b2);
    pool_kernel<<<dim3(C_, B_, 2), 256>>>(orig_len);
    fc_kernel<<<1, 64>>>(fcw, fcb, out);
}